// round 10
// baseline (speedup 1.0000x reference)
#include <cuda_runtime.h>
#include <cstdint>

#define FULLMASK 0xffffffffu
typedef unsigned long long u64;

// ---- f32x2 packed helpers (sm_103a) ----
__device__ __forceinline__ u64 pk2(float lo, float hi) {
    u64 r; asm("mov.b64 %0,{%1,%2};" : "=l"(r) : "f"(lo), "f"(hi)); return r;
}
__device__ __forceinline__ void up2(u64 v, float& lo, float& hi) {
    asm("mov.b64 {%0,%1},%2;" : "=f"(lo), "=f"(hi) : "l"(v));
}
__device__ __forceinline__ u64 fma2(u64 a, u64 b, u64 c) {
    u64 d; asm("fma.rn.f32x2 %0,%1,%2,%3;" : "=l"(d) : "l"(a), "l"(b), "l"(c)); return d;
}
__device__ __forceinline__ u64 mul2(u64 a, u64 b) {
    u64 d; asm("mul.rn.f32x2 %0,%1,%2;" : "=l"(d) : "l"(a), "l"(b)); return d;
}
__device__ __forceinline__ u64 add2(u64 a, u64 b) {
    u64 d; asm("add.rn.f32x2 %0,%1,%2;" : "=l"(d) : "l"(a), "l"(b)); return d;
}
__device__ __forceinline__ u64 neg2(u64 a) { return a ^ 0x8000000080000000ULL; }

// Inter-kernel scratch: per-row (cos, sin) of angle/2, [B][8] float2 (B <= 131072)
__device__ float2 d_cs[131072 * 8];

// ============ Kernel 1: LN + linear -> (cos, sin)(angle/2), fully f32x2-packed ============
// 4 rows per warp (8 lanes/row in load stage), routed reduce; each lane ends with
// all 10 sums of row (lane>>3), computes angle (lane&7), writes (cos, sin).
__global__ __launch_bounds__(256, 2) void angles_kernel(const float* __restrict__ E,
                                                        const float* __restrict__ W_pre,
                                                        const float* __restrict__ ln_gamma,
                                                        const float* __restrict__ ln_beta,
                                                        const float* __restrict__ b_pre,
                                                        int B) {
    __shared__ float4 sWg4[8 * 128];  // 16 KB: gamma ⊙ W_pre
    __shared__ float sGw[32], sBw[32];
    __shared__ float sSg[8], sCq[8];

    int tid = threadIdx.x;
    int lane = tid & 31;
    int wrp = tid >> 5;
    const float4* Wp4 = (const float4*)W_pre;
    const float4* g4  = (const float4*)ln_gamma;
    const float4* b4  = (const float4*)ln_beta;

    // Fill Wg smem; fold per-block Sg (= gamma·W[q]) and Cq (= beta·W[q] + b_pre).
    float gw[4], bw[4];
    #pragma unroll
    for (int j = 0; j < 4; j++) {
        int i = tid + 256 * j;
        float4 w = Wp4[i];
        float4 g = g4[i & 127];
        float4 b = b4[i & 127];
        float gsum = 0.f, bsum = 0.f;
        gsum = fmaf(g.x, w.x, gsum); gsum = fmaf(g.y, w.y, gsum);
        gsum = fmaf(g.z, w.z, gsum); gsum = fmaf(g.w, w.w, gsum);
        bsum = fmaf(b.x, w.x, bsum); bsum = fmaf(b.y, w.y, bsum);
        bsum = fmaf(b.z, w.z, bsum); bsum = fmaf(b.w, w.w, bsum);
        gw[j] = gsum; bw[j] = bsum;
        w.x *= g.x; w.y *= g.y; w.z *= g.z; w.w *= g.w;
        sWg4[i] = w;
    }
    #pragma unroll
    for (int m = 16; m; m >>= 1) {
        #pragma unroll
        for (int j = 0; j < 4; j++) {
            gw[j] += __shfl_xor_sync(FULLMASK, gw[j], m);
            bw[j] += __shfl_xor_sync(FULLMASK, bw[j], m);
        }
    }
    if (lane == 0) {
        #pragma unroll
        for (int j = 0; j < 4; j++) {
            sGw[wrp * 4 + j] = gw[j];
            sBw[wrp * 4 + j] = bw[j];
        }
    }
    __syncthreads();
    if (tid < 8) {
        int h = tid & 1, jj = tid >> 1;
        float s = 0.f, cc = 0.f;
        #pragma unroll
        for (int m = 0; m < 4; m++) {
            s  += sGw[(4 * h + m) * 4 + jj];
            cc += sBw[(4 * h + m) * 4 + jj];
        }
        sSg[tid] = s;
        sCq[tid] = cc + b_pre[tid];
    }
    __syncthreads();

    int warp = blockIdx.x * 8 + wrp;
    int row0 = warp * 4;

    // Packed accumulators: S2 sum, SS2 sumsq, D2[q] dots
    u64 S2[4], SS2[4], D2[4][8];
    #pragma unroll
    for (int rr = 0; rr < 4; rr++) {
        S2[rr] = 0; SS2[rr] = 0;
        #pragma unroll
        for (int q = 0; q < 8; q++) D2[rr][q] = 0;
    }

    const ulonglong2* er[4];
    #pragma unroll
    for (int rr = 0; rr < 4; rr++) {
        int r = row0 + rr;
        if (r >= B) r = B - 1;
        er[rr] = (const ulonglong2*)(E + (size_t)r * 512);
    }
    const ulonglong2* sWgU = (const ulonglong2*)sWg4;

    #pragma unroll
    for (int j = 0; j < 4; j++) {
        ulonglong2 e[4];
        #pragma unroll
        for (int rr = 0; rr < 4; rr++) e[rr] = __ldcs(&er[rr][j * 32 + lane]);
        #pragma unroll
        for (int rr = 0; rr < 4; rr++) {
            S2[rr]  = add2(S2[rr], add2(e[rr].x, e[rr].y));
            SS2[rr] = fma2(e[rr].x, e[rr].x, fma2(e[rr].y, e[rr].y, SS2[rr]));
        }
        #pragma unroll
        for (int q = 0; q < 8; q++) {
            ulonglong2 w = sWgU[q * 128 + j * 32 + lane];
            #pragma unroll
            for (int rr = 0; rr < 4; rr++)
                D2[rr][q] = fma2(e[rr].x, w.x, fma2(e[rr].y, w.y, D2[rr][q]));
        }
    }

    // Horizontal collapse to scalars, then routed reduction (verified)
    float V[4][10];
    #pragma unroll
    for (int rr = 0; rr < 4; rr++) {
        float lo, hi;
        up2(S2[rr], lo, hi);  V[rr][0] = lo + hi;
        up2(SS2[rr], lo, hi); V[rr][1] = lo + hi;
        #pragma unroll
        for (int q = 0; q < 8; q++) {
            up2(D2[rr][q], lo, hi);
            V[rr][2 + q] = lo + hi;
        }
    }

    #pragma unroll
    for (int rr = 0; rr < 4; rr++)
        #pragma unroll
        for (int k = 0; k < 10; k++)
            V[rr][k] += __shfl_xor_sync(FULLMASK, V[rr][k], 16);
    bool up = (lane & 16) != 0;
    #pragma unroll
    for (int k = 0; k < 10; k++) {
        V[0][k] = up ? V[2][k] : V[0][k];
        V[1][k] = up ? V[3][k] : V[1][k];
    }
    #pragma unroll
    for (int k = 0; k < 10; k++) {
        V[0][k] += __shfl_xor_sync(FULLMASK, V[0][k], 8);
        V[1][k] += __shfl_xor_sync(FULLMASK, V[1][k], 8);
    }
    bool sel1 = (lane & 8) != 0;
    float A[10];
    #pragma unroll
    for (int k = 0; k < 10; k++) {
        float v = sel1 ? V[1][k] : V[0][k];
        v += __shfl_xor_sync(FULLMASK, v, 4);
        v += __shfl_xor_sync(FULLMASK, v, 2);
        v += __shfl_xor_sync(FULLMASK, v, 1);
        A[k] = v;
    }

    const float inv512 = 1.0f / 512.0f;
    float mu = A[0] * inv512;
    float var = fmaf(-mu, mu, A[1] * inv512);
    float inv = rsqrtf(var + 1e-5f);

    int j = lane & 7;
    int row = row0 + (lane >> 3);
    float ang = fmaf(inv, fmaf(-mu, sSg[j], A[2 + j]), sCq[j]);
    float s, c;
    __sincosf(0.5f * ang, &s, &c);
    if (row < B) d_cs[row * 8 + j] = make_float2(c, s);
}

// ============ Kernel 2: circuit + readout (unchanged from R9, verified) ============
__global__ __launch_bounds__(256, 2) void circuit_kernel(float* __restrict__ out,
                                                         const float* __restrict__ theta,
                                                         const float* __restrict__ W_post,
                                                         const float* __restrict__ b_post,
                                                         int B) {
    __shared__ __align__(16) float2 sG2[4 * 34];
    __shared__ float sct[8], sst[8], sbp;

    int tid = threadIdx.x;
    if (tid < 8) {
        float h = 0.5f * theta[tid];
        sct[tid] = cosf(h);
        sst[tid] = sinf(h);
    }
    if (tid < 128) {
        int lsub = tid >> 5, r = tid & 31;
        int bb0 = r | (lsub << 6);
        int bb1 = bb0 | 32;
        float g0 = 0.f, g1 = 0.f;
        #pragma unroll
        for (int i = 0; i < 8; i++) {
            float w = W_post[i];
            g0 += w * (((bb0 >> i) & 1) ? -1.f : 1.f);
            g1 += w * (((bb1 >> i) & 1) ? -1.f : 1.f);
        }
        sG2[lsub * 34 + r] = make_float2(g0, g1);
    }
    if (tid == 0) sbp = b_post[0];
    __syncthreads();

    int lane = tid & 31;
    int warp = blockIdx.x * 8 + (tid >> 5);
    int myrow = warp * 8 + (lane >> 2);
    int rowc = myrow < B ? myrow : (B - 1);

    const float4* ap = (const float4*)(d_cs + (size_t)rowc * 8);
    float4 v0 = ap[0], v1 = ap[1], v2 = ap[2], v3 = ap[3];
    float ca[8], sa[8];
    ca[0] = v0.x; sa[0] = v0.y; ca[1] = v0.z; sa[1] = v0.w;
    ca[2] = v1.x; sa[2] = v1.y; ca[3] = v1.z; sa[3] = v1.w;
    ca[4] = v2.x; sa[4] = v2.y; ca[5] = v2.z; sa[5] = v2.w;
    ca[6] = v3.x; sa[6] = v3.y; ca[7] = v3.z; sa[7] = v3.w;

    int b6 = lane & 1;
    int b7 = (lane >> 1) & 1;
    int lbase = lane & ~3;
    int s0 = lbase | b6 | ((b7 ^ b6) << 1);
    int s1 = s0 ^ 1;

    u64 amp2[32];
    {
        float w67 = (b6 ? sa[6] : ca[6]) * (b7 ? sa[7] : ca[7]);
        amp2[0] = pk2(w67 * ca[5], w67 * sa[5]);
        #pragma unroll
        for (int q = 0; q < 5; q++) {
            u64 cab = pk2(ca[q], ca[q]);
            u64 sab = pk2(sa[q], sa[q]);
            const int cnt = 1 << q;
            #pragma unroll
            for (int r = 0; r < 16; r++) {
                if (r < cnt) {
                    amp2[r + cnt] = mul2(amp2[r], sab);
                    amp2[r]       = mul2(amp2[r], cab);
                }
            }
        }
    }

    float ct[8], st[8];
    #pragma unroll
    for (int q = 0; q < 8; q++) { ct[q] = sct[q]; st[q] = sst[q]; }
    float sg6 = b6 ? st[6] : -st[6];
    float sg7 = b7 ? st[7] : -st[7];
    float k00 = b7 ? -st[0] : ct[0];
    float k01 = b7 ? ct[0] : -st[0];
    float k10 = b7 ? ct[0] : st[0];
    float k11 = b7 ? st[0] : ct[0];
    u64 K00b = pk2(k00, k00), K01b = pk2(k01, k01);
    u64 K10b = pk2(k10, k10), K11b = pk2(k11, k11);
    u64 cb[5], psb[5];
    #pragma unroll
    for (int q = 1; q < 5; q++) {
        cb[q]  = pk2(ct[q], ct[q]);
        psb[q] = pk2(st[q], st[q]);
    }
    u64 cb5   = pk2(ct[5], ct[5]);
    u64 sgn5b = pk2(-st[5], st[5]);
    u64 ct6b = pk2(ct[6], ct[6]), sg6b = pk2(sg6, sg6);
    u64 ct7b = pk2(ct[7], ct[7]), sg7b = pk2(sg7, sg7);

    #pragma unroll
    for (int d = 0; d < 2; d++) {
        #pragma unroll
        for (int r = 0; r < 32; r++)
            if ((r & 1) && !(r & 2)) { u64 t = amp2[r]; amp2[r] = amp2[r | 2]; amp2[r | 2] = t; }
        #pragma unroll
        for (int r = 0; r < 32; r++)
            if ((r & 2) && !(r & 4)) { u64 t = amp2[r]; amp2[r] = amp2[r | 4]; amp2[r | 4] = t; }
        #pragma unroll
        for (int r = 0; r < 32; r++)
            if ((r & 4) && !(r & 8)) { u64 t = amp2[r]; amp2[r] = amp2[r | 8]; amp2[r | 8] = t; }
        #pragma unroll
        for (int r = 0; r < 32; r++)
            if ((r & 8) && !(r & 16)) { u64 t = amp2[r]; amp2[r] = amp2[r | 16]; amp2[r | 16] = t; }
        #pragma unroll
        for (int r = 0; r < 32; r++) {
            float lo, hi;
            up2(amp2[r], lo, hi);
            float x0 = (r & 16) ? hi : lo;
            float x1 = (r & 16) ? lo : hi;
            float nlo = __shfl_sync(FULLMASK, x0, s0);
            float nhi = __shfl_sync(FULLMASK, x1, s1);
            amp2[r] = pk2(nlo, nhi);
        }
        #pragma unroll
        for (int r = 0; r < 32; r += 2) {
            u64 a0 = amp2[r], a1 = amp2[r + 1];
            amp2[r]     = fma2(K00b, a0, mul2(K01b, a1));
            amp2[r + 1] = fma2(K10b, a0, mul2(K11b, a1));
        }
        #pragma unroll
        for (int q = 1; q < 5; q++) {
            const int bq = 1 << q;
            #pragma unroll
            for (int r = 0; r < 32; r++) {
                if (!(r & bq)) {
                    int r2 = r | bq;
                    u64 a0 = amp2[r], a1 = amp2[r2];
                    amp2[r]  = fma2(psb[q], neg2(a1), mul2(cb[q], a0));
                    amp2[r2] = fma2(psb[q], a0, mul2(cb[q], a1));
                }
            }
        }
        #pragma unroll
        for (int r = 0; r < 32; r++) {
            float lo, hi;
            up2(amp2[r], lo, hi);
            u64 vs = pk2(hi, lo);
            amp2[r] = fma2(sgn5b, vs, mul2(cb5, amp2[r]));
        }
        #pragma unroll
        for (int r = 0; r < 32; r++) {
            float lo, hi;
            up2(amp2[r], lo, hi);
            float plo = __shfl_xor_sync(FULLMASK, lo, 1);
            float phi = __shfl_xor_sync(FULLMASK, hi, 1);
            amp2[r] = fma2(sg6b, pk2(plo, phi), mul2(ct6b, amp2[r]));
        }
        #pragma unroll
        for (int r = 0; r < 32; r++) {
            float lo, hi;
            up2(amp2[r], lo, hi);
            float plo = __shfl_xor_sync(FULLMASK, lo, 2);
            float phi = __shfl_xor_sync(FULLMASK, hi, 2);
            amp2[r] = fma2(sg7b, pk2(plo, phi), mul2(ct7b, amp2[r]));
        }
    }

    int lsub = lane & 3;
    const u64* gp = (const u64*)(sG2 + lsub * 34);
    u64 tot2 = pk2(0.f, 0.f);
    #pragma unroll
    for (int r = 0; r < 32; r++) {
        u64 p2 = mul2(amp2[r], amp2[r]);
        tot2 = fma2(p2, gp[r], tot2);
    }
    float tlo, thi;
    up2(tot2, tlo, thi);
    float tot = tlo + thi;
    tot += __shfl_xor_sync(FULLMASK, tot, 1);
    tot += __shfl_xor_sync(FULLMASK, tot, 2);

    if (lsub == 0 && myrow < B)
        out[myrow] = tot + sbp;
}

extern "C" void kernel_launch(void* const* d_in, const int* in_sizes, int n_in,
                              void* d_out, int out_size) {
    const float* E        = (const float*)d_in[0];
    const float* ln_gamma = (const float*)d_in[1];
    const float* ln_beta  = (const float*)d_in[2];
    const float* W_pre    = (const float*)d_in[3];
    const float* b_pre    = (const float*)d_in[4];
    const float* theta    = (const float*)d_in[5];
    const float* W_post   = (const float*)d_in[6];
    const float* b_post   = (const float*)d_in[7];
    float* out = (float*)d_out;
    int B = out_size;

    angles_kernel<<<(B + 31) / 32, 256>>>(E, W_pre, ln_gamma, ln_beta, b_pre, B);
    circuit_kernel<<<(B + 63) / 64, 256>>>(out, theta, W_post, b_post, B);
}

// round 11
// speedup vs baseline: 1.0807x; 1.0807x over previous
#include <cuda_runtime.h>
#include <cstdint>

#define FULLMASK 0xffffffffu
typedef unsigned long long u64;

// ---- f32x2 packed helpers (sm_103a) ----
__device__ __forceinline__ u64 pk2(float lo, float hi) {
    u64 r; asm("mov.b64 %0,{%1,%2};" : "=l"(r) : "f"(lo), "f"(hi)); return r;
}
__device__ __forceinline__ void up2(u64 v, float& lo, float& hi) {
    asm("mov.b64 {%0,%1},%2;" : "=f"(lo), "=f"(hi) : "l"(v));
}
__device__ __forceinline__ u64 fma2(u64 a, u64 b, u64 c) {
    u64 d; asm("fma.rn.f32x2 %0,%1,%2,%3;" : "=l"(d) : "l"(a), "l"(b), "l"(c)); return d;
}
__device__ __forceinline__ u64 mul2(u64 a, u64 b) {
    u64 d; asm("mul.rn.f32x2 %0,%1,%2;" : "=l"(d) : "l"(a), "l"(b)); return d;
}

// Inter-kernel scratch: per-row (cos, sin) of angle/2, [B][8] float2 (B <= 131072)
__device__ float2 d_cs[131072 * 8];

// ============ Kernel 1: LN + linear -> (cos, sin)(angle/2) — R9 scalar version ============
__global__ __launch_bounds__(256, 2) void angles_kernel(const float* __restrict__ E,
                                                        const float* __restrict__ W_pre,
                                                        const float* __restrict__ ln_gamma,
                                                        const float* __restrict__ ln_beta,
                                                        const float* __restrict__ b_pre,
                                                        int B) {
    __shared__ float4 sWg4[8 * 128];  // 16 KB: gamma ⊙ W_pre
    __shared__ float sGw[32], sBw[32];
    __shared__ float sSg[8], sCq[8];

    int tid = threadIdx.x;
    int lane = tid & 31;
    int wrp = tid >> 5;
    const float4* Wp4 = (const float4*)W_pre;
    const float4* g4  = (const float4*)ln_gamma;
    const float4* b4  = (const float4*)ln_beta;

    float gw[4], bw[4];
    #pragma unroll
    for (int j = 0; j < 4; j++) {
        int i = tid + 256 * j;
        float4 w = Wp4[i];
        float4 g = g4[i & 127];
        float4 b = b4[i & 127];
        float gsum = 0.f, bsum = 0.f;
        gsum = fmaf(g.x, w.x, gsum); gsum = fmaf(g.y, w.y, gsum);
        gsum = fmaf(g.z, w.z, gsum); gsum = fmaf(g.w, w.w, gsum);
        bsum = fmaf(b.x, w.x, bsum); bsum = fmaf(b.y, w.y, bsum);
        bsum = fmaf(b.z, w.z, bsum); bsum = fmaf(b.w, w.w, bsum);
        gw[j] = gsum; bw[j] = bsum;
        w.x *= g.x; w.y *= g.y; w.z *= g.z; w.w *= g.w;
        sWg4[i] = w;
    }
    #pragma unroll
    for (int m = 16; m; m >>= 1) {
        #pragma unroll
        for (int j = 0; j < 4; j++) {
            gw[j] += __shfl_xor_sync(FULLMASK, gw[j], m);
            bw[j] += __shfl_xor_sync(FULLMASK, bw[j], m);
        }
    }
    if (lane == 0) {
        #pragma unroll
        for (int j = 0; j < 4; j++) {
            sGw[wrp * 4 + j] = gw[j];
            sBw[wrp * 4 + j] = bw[j];
        }
    }
    __syncthreads();
    if (tid < 8) {
        int h = tid & 1, jj = tid >> 1;
        float s = 0.f, cc = 0.f;
        #pragma unroll
        for (int m = 0; m < 4; m++) {
            s  += sGw[(4 * h + m) * 4 + jj];
            cc += sBw[(4 * h + m) * 4 + jj];
        }
        sSg[tid] = s;
        sCq[tid] = cc + b_pre[tid];
    }
    __syncthreads();

    int warp = blockIdx.x * 8 + wrp;
    int row0 = warp * 4;

    float V[4][10];
    #pragma unroll
    for (int rr = 0; rr < 4; rr++)
        #pragma unroll
        for (int k = 0; k < 10; k++) V[rr][k] = 0.f;

    const float4* er[4];
    #pragma unroll
    for (int rr = 0; rr < 4; rr++) {
        int r = row0 + rr;
        if (r >= B) r = B - 1;
        er[rr] = (const float4*)(E + (size_t)r * 512);
    }

    #pragma unroll
    for (int j = 0; j < 4; j++) {
        float4 e[4];
        #pragma unroll
        for (int rr = 0; rr < 4; rr++) e[rr] = __ldcs(&er[rr][j * 32 + lane]);
        #pragma unroll
        for (int rr = 0; rr < 4; rr++) {
            V[rr][0] += (e[rr].x + e[rr].y) + (e[rr].z + e[rr].w);
            float ssv = V[rr][1];
            ssv = fmaf(e[rr].x, e[rr].x, ssv);
            ssv = fmaf(e[rr].y, e[rr].y, ssv);
            ssv = fmaf(e[rr].z, e[rr].z, ssv);
            ssv = fmaf(e[rr].w, e[rr].w, ssv);
            V[rr][1] = ssv;
        }
        #pragma unroll
        for (int q = 0; q < 8; q++) {
            float4 wv = sWg4[q * 128 + j * 32 + lane];
            #pragma unroll
            for (int rr = 0; rr < 4; rr++) {
                float a = V[rr][2 + q];
                a = fmaf(e[rr].x, wv.x, a);
                a = fmaf(e[rr].y, wv.y, a);
                a = fmaf(e[rr].z, wv.z, a);
                a = fmaf(e[rr].w, wv.w, a);
                V[rr][2 + q] = a;
            }
        }
    }

    #pragma unroll
    for (int rr = 0; rr < 4; rr++)
        #pragma unroll
        for (int k = 0; k < 10; k++)
            V[rr][k] += __shfl_xor_sync(FULLMASK, V[rr][k], 16);
    bool up = (lane & 16) != 0;
    #pragma unroll
    for (int k = 0; k < 10; k++) {
        V[0][k] = up ? V[2][k] : V[0][k];
        V[1][k] = up ? V[3][k] : V[1][k];
    }
    #pragma unroll
    for (int k = 0; k < 10; k++) {
        V[0][k] += __shfl_xor_sync(FULLMASK, V[0][k], 8);
        V[1][k] += __shfl_xor_sync(FULLMASK, V[1][k], 8);
    }
    bool sel1 = (lane & 8) != 0;
    float A[10];
    #pragma unroll
    for (int k = 0; k < 10; k++) {
        float v = sel1 ? V[1][k] : V[0][k];
        v += __shfl_xor_sync(FULLMASK, v, 4);
        v += __shfl_xor_sync(FULLMASK, v, 2);
        v += __shfl_xor_sync(FULLMASK, v, 1);
        A[k] = v;
    }

    const float inv512 = 1.0f / 512.0f;
    float mu = A[0] * inv512;
    float var = fmaf(-mu, mu, A[1] * inv512);
    float inv = rsqrtf(var + 1e-5f);

    int j = lane & 7;
    int row = row0 + (lane >> 3);
    float ang = fmaf(inv, fmaf(-mu, sSg[j], A[2 + j]), sCq[j]);
    float s, c;
    __sincosf(0.5f * ang, &s, &c);
    if (row < B) d_cs[row * 8 + j] = make_float2(c, s);
}

// ============ Kernel 2: circuit + readout, tan-form rotations ============
// RY(theta) = c·(I + t·J); global cos factors folded into g table as F^2.
// 4 lanes/row (lane bit0 = q6, bit1 = q7); 32 x f32x2, pair bit = q5.
__global__ __launch_bounds__(256, 2) void circuit_kernel(float* __restrict__ out,
                                                         const float* __restrict__ theta,
                                                         const float* __restrict__ W_post,
                                                         const float* __restrict__ b_post,
                                                         int B) {
    __shared__ __align__(16) float2 sG2[4 * 34];
    __shared__ float sct[8], sst[8], sbp;

    int tid = threadIdx.x;
    if (tid < 8) {
        float h = 0.5f * theta[tid];
        sct[tid] = cosf(h);
        sst[tid] = sinf(h);
    }
    if (tid < 128) {
        // amp scale F = prod_q c_q^2 (8 gates x 2 depths); prob scale F^2
        float fa = 1.f;
        #pragma unroll
        for (int i = 0; i < 8; i++) {
            float cc = cosf(0.5f * theta[i]);
            fa *= cc * cc;
        }
        float scale = fa * fa;
        int lsub = tid >> 5, r = tid & 31;
        int bb0 = r | (lsub << 6);
        int bb1 = bb0 | 32;
        float g0 = 0.f, g1 = 0.f;
        #pragma unroll
        for (int i = 0; i < 8; i++) {
            float w = W_post[i];
            g0 += w * (((bb0 >> i) & 1) ? -1.f : 1.f);
            g1 += w * (((bb1 >> i) & 1) ? -1.f : 1.f);
        }
        sG2[lsub * 34 + r] = make_float2(g0 * scale, g1 * scale);
    }
    if (tid == 0) sbp = b_post[0];
    __syncthreads();

    int lane = tid & 31;
    int warp = blockIdx.x * 8 + (tid >> 5);
    int myrow = warp * 8 + (lane >> 2);
    int rowc = myrow < B ? myrow : (B - 1);

    const float4* ap = (const float4*)(d_cs + (size_t)rowc * 8);
    float4 v0 = ap[0], v1 = ap[1], v2 = ap[2], v3 = ap[3];
    float ca[8], sa[8];
    ca[0] = v0.x; sa[0] = v0.y; ca[1] = v0.z; sa[1] = v0.w;
    ca[2] = v1.x; sa[2] = v1.y; ca[3] = v1.z; sa[3] = v1.w;
    ca[4] = v2.x; sa[4] = v2.y; ca[5] = v2.z; sa[5] = v2.w;
    ca[6] = v3.x; sa[6] = v3.y; ca[7] = v3.z; sa[7] = v3.w;

    int b6 = lane & 1;
    int b7 = (lane >> 1) & 1;
    bool c7 = b7 != 0;
    int lbase = lane & ~3;
    int s0 = lbase | b6 | ((b7 ^ b6) << 1);
    int s1 = s0 ^ 1;

    // Initial product state (packed over qubit5)
    u64 amp2[32];
    {
        float w67 = (b6 ? sa[6] : ca[6]) * (b7 ? sa[7] : ca[7]);
        amp2[0] = pk2(w67 * ca[5], w67 * sa[5]);
        #pragma unroll
        for (int q = 0; q < 5; q++) {
            u64 cab = pk2(ca[q], ca[q]);
            u64 sab = pk2(sa[q], sa[q]);
            const int cnt = 1 << q;
            #pragma unroll
            for (int r = 0; r < 16; r++) {
                if (r < cnt) {
                    amp2[r + cnt] = mul2(amp2[r], sab);
                    amp2[r]       = mul2(amp2[r], cab);
                }
            }
        }
    }

    // tan-form constants
    float tq[8];
    #pragma unroll
    for (int q = 0; q < 8; q++) tq[q] = sst[q] / sct[q];
    u64 nt0b = pk2(-tq[0], -tq[0]), pt0b = pk2(tq[0], tq[0]);
    u64 ntb[5], ptb[5];
    #pragma unroll
    for (int q = 1; q < 5; q++) {
        ntb[q] = pk2(-tq[q], -tq[q]);
        ptb[q] = pk2(tq[q], tq[q]);
    }
    u64 t5v = pk2(-tq[5], tq[5]);
    float sg6t = b6 ? tq[6] : -tq[6];
    float sg7t = b7 ? tq[7] : -tq[7];
    u64 sg6tb = pk2(sg6t, sg6t);
    u64 sg7tb = pk2(sg7t, sg7t);

    #pragma unroll
    for (int d = 0; d < 2; d++) {
        // CNOT(0,1)..(3,4): pair-level register renames (free)
        #pragma unroll
        for (int r = 0; r < 32; r++)
            if ((r & 1) && !(r & 2)) { u64 t = amp2[r]; amp2[r] = amp2[r | 2]; amp2[r | 2] = t; }
        #pragma unroll
        for (int r = 0; r < 32; r++)
            if ((r & 2) && !(r & 4)) { u64 t = amp2[r]; amp2[r] = amp2[r | 4]; amp2[r | 4] = t; }
        #pragma unroll
        for (int r = 0; r < 32; r++)
            if ((r & 4) && !(r & 8)) { u64 t = amp2[r]; amp2[r] = amp2[r | 8]; amp2[r | 8] = t; }
        #pragma unroll
        for (int r = 0; r < 32; r++)
            if ((r & 8) && !(r & 16)) { u64 t = amp2[r]; amp2[r] = amp2[r | 16]; amp2[r | 16] = t; }
        // CNOT(4,5) absorbed half-swap + merged CNOT(5,6)+(6,7) lane gather
        #pragma unroll
        for (int r = 0; r < 32; r++) {
            float lo, hi;
            up2(amp2[r], lo, hi);
            float x0 = (r & 16) ? hi : lo;
            float x1 = (r & 16) ? lo : hi;
            float nlo = __shfl_sync(FULLMASK, x0, s0);
            float nhi = __shfl_sync(FULLMASK, x1, s1);
            amp2[r] = pk2(nlo, nhi);
        }
        // fused CNOT(7,0)+RY(0), tan form: swap via SEL (ALU), then I + t·J
        #pragma unroll
        for (int r = 0; r < 32; r += 2) {
            u64 a0 = amp2[r], a1 = amp2[r + 1];
            u64 x0 = c7 ? a1 : a0;
            u64 x1 = c7 ? a0 : a1;
            amp2[r]     = fma2(nt0b, x1, x0);
            amp2[r + 1] = fma2(pt0b, x0, x1);
        }
        // RY on qubits 1..4, tan form: 2 fma2 per pair
        #pragma unroll
        for (int q = 1; q < 5; q++) {
            const int bq = 1 << q;
            #pragma unroll
            for (int r = 0; r < 32; r++) {
                if (!(r & bq)) {
                    int r2 = r | bq;
                    u64 a0 = amp2[r], a1 = amp2[r2];
                    amp2[r]  = fma2(ntb[q], a1, a0);
                    amp2[r2] = fma2(ptb[q], a0, a1);
                }
            }
        }
        // RY(5), tan form: 1 fma2 per reg
        #pragma unroll
        for (int r = 0; r < 32; r++) {
            float lo, hi;
            up2(amp2[r], lo, hi);
            u64 vs = pk2(hi, lo);
            amp2[r] = fma2(t5v, vs, amp2[r]);
        }
        // RY(6): lane xor1, tan form
        #pragma unroll
        for (int r = 0; r < 32; r++) {
            float lo, hi;
            up2(amp2[r], lo, hi);
            float plo = __shfl_xor_sync(FULLMASK, lo, 1);
            float phi = __shfl_xor_sync(FULLMASK, hi, 1);
            amp2[r] = fma2(sg6tb, pk2(plo, phi), amp2[r]);
        }
        // RY(7): lane xor2, tan form
        #pragma unroll
        for (int r = 0; r < 32; r++) {
            float lo, hi;
            up2(amp2[r], lo, hi);
            float plo = __shfl_xor_sync(FULLMASK, lo, 2);
            float phi = __shfl_xor_sync(FULLMASK, hi, 2);
            amp2[r] = fma2(sg7tb, pk2(plo, phi), amp2[r]);
        }
    }

    // ---------------- Readout (packed; g table carries F^2) ----------------
    int lsub = lane & 3;
    const u64* gp = (const u64*)(sG2 + lsub * 34);
    u64 tot2 = pk2(0.f, 0.f);
    #pragma unroll
    for (int r = 0; r < 32; r++) {
        u64 p2 = mul2(amp2[r], amp2[r]);
        tot2 = fma2(p2, gp[r], tot2);
    }
    float tlo, thi;
    up2(tot2, tlo, thi);
    float tot = tlo + thi;
    tot += __shfl_xor_sync(FULLMASK, tot, 1);
    tot += __shfl_xor_sync(FULLMASK, tot, 2);

    if (lsub == 0 && myrow < B)
        out[myrow] = tot + sbp;
}

extern "C" void kernel_launch(void* const* d_in, const int* in_sizes, int n_in,
                              void* d_out, int out_size) {
    const float* E        = (const float*)d_in[0];
    const float* ln_gamma = (const float*)d_in[1];
    const float* ln_beta  = (const float*)d_in[2];
    const float* W_pre    = (const float*)d_in[3];
    const float* b_pre    = (const float*)d_in[4];
    const float* theta    = (const float*)d_in[5];
    const float* W_post   = (const float*)d_in[6];
    const float* b_post   = (const float*)d_in[7];
    float* out = (float*)d_out;
    int B = out_size;

    angles_kernel<<<(B + 31) / 32, 256>>>(E, W_pre, ln_gamma, ln_beta, b_pre, B);
    circuit_kernel<<<(B + 63) / 64, 256>>>(out, theta, W_post, b_post, B);
}

// round 12
// speedup vs baseline: 1.1195x; 1.0360x over previous
#include <cuda_runtime.h>
#include <cstdint>

#define FULLMASK 0xffffffffu
typedef unsigned long long u64;

// ---- f32x2 packed helpers (sm_103a) ----
__device__ __forceinline__ u64 pk2(float lo, float hi) {
    u64 r; asm("mov.b64 %0,{%1,%2};" : "=l"(r) : "f"(lo), "f"(hi)); return r;
}
__device__ __forceinline__ void up2(u64 v, float& lo, float& hi) {
    asm("mov.b64 {%0,%1},%2;" : "=f"(lo), "=f"(hi) : "l"(v));
}
__device__ __forceinline__ u64 fma2(u64 a, u64 b, u64 c) {
    u64 d; asm("fma.rn.f32x2 %0,%1,%2,%3;" : "=l"(d) : "l"(a), "l"(b), "l"(c)); return d;
}
__device__ __forceinline__ u64 mul2(u64 a, u64 b) {
    u64 d; asm("mul.rn.f32x2 %0,%1,%2;" : "=l"(d) : "l"(a), "l"(b)); return d;
}

// Inter-kernel scratch: per-row (cos, sin) of angle/2, [B][8] float2 (B <= 131072)
__device__ float2 d_cs[131072 * 8];

// ============ Kernel 1: LN + linear -> (cos, sin)(angle/2) — unchanged (R11) ============
__global__ __launch_bounds__(256, 2) void angles_kernel(const float* __restrict__ E,
                                                        const float* __restrict__ W_pre,
                                                        const float* __restrict__ ln_gamma,
                                                        const float* __restrict__ ln_beta,
                                                        const float* __restrict__ b_pre,
                                                        int B) {
    __shared__ float4 sWg4[8 * 128];  // 16 KB: gamma ⊙ W_pre
    __shared__ float sGw[32], sBw[32];
    __shared__ float sSg[8], sCq[8];

    int tid = threadIdx.x;
    int lane = tid & 31;
    int wrp = tid >> 5;
    const float4* Wp4 = (const float4*)W_pre;
    const float4* g4  = (const float4*)ln_gamma;
    const float4* b4  = (const float4*)ln_beta;

    float gw[4], bw[4];
    #pragma unroll
    for (int j = 0; j < 4; j++) {
        int i = tid + 256 * j;
        float4 w = Wp4[i];
        float4 g = g4[i & 127];
        float4 b = b4[i & 127];
        float gsum = 0.f, bsum = 0.f;
        gsum = fmaf(g.x, w.x, gsum); gsum = fmaf(g.y, w.y, gsum);
        gsum = fmaf(g.z, w.z, gsum); gsum = fmaf(g.w, w.w, gsum);
        bsum = fmaf(b.x, w.x, bsum); bsum = fmaf(b.y, w.y, bsum);
        bsum = fmaf(b.z, w.z, bsum); bsum = fmaf(b.w, w.w, bsum);
        gw[j] = gsum; bw[j] = bsum;
        w.x *= g.x; w.y *= g.y; w.z *= g.z; w.w *= g.w;
        sWg4[i] = w;
    }
    #pragma unroll
    for (int m = 16; m; m >>= 1) {
        #pragma unroll
        for (int j = 0; j < 4; j++) {
            gw[j] += __shfl_xor_sync(FULLMASK, gw[j], m);
            bw[j] += __shfl_xor_sync(FULLMASK, bw[j], m);
        }
    }
    if (lane == 0) {
        #pragma unroll
        for (int j = 0; j < 4; j++) {
            sGw[wrp * 4 + j] = gw[j];
            sBw[wrp * 4 + j] = bw[j];
        }
    }
    __syncthreads();
    if (tid < 8) {
        int h = tid & 1, jj = tid >> 1;
        float s = 0.f, cc = 0.f;
        #pragma unroll
        for (int m = 0; m < 4; m++) {
            s  += sGw[(4 * h + m) * 4 + jj];
            cc += sBw[(4 * h + m) * 4 + jj];
        }
        sSg[tid] = s;
        sCq[tid] = cc + b_pre[tid];
    }
    __syncthreads();

    int warp = blockIdx.x * 8 + wrp;
    int row0 = warp * 4;

    float V[4][10];
    #pragma unroll
    for (int rr = 0; rr < 4; rr++)
        #pragma unroll
        for (int k = 0; k < 10; k++) V[rr][k] = 0.f;

    const float4* er[4];
    #pragma unroll
    for (int rr = 0; rr < 4; rr++) {
        int r = row0 + rr;
        if (r >= B) r = B - 1;
        er[rr] = (const float4*)(E + (size_t)r * 512);
    }

    #pragma unroll
    for (int j = 0; j < 4; j++) {
        float4 e[4];
        #pragma unroll
        for (int rr = 0; rr < 4; rr++) e[rr] = __ldcs(&er[rr][j * 32 + lane]);
        #pragma unroll
        for (int rr = 0; rr < 4; rr++) {
            V[rr][0] += (e[rr].x + e[rr].y) + (e[rr].z + e[rr].w);
            float ssv = V[rr][1];
            ssv = fmaf(e[rr].x, e[rr].x, ssv);
            ssv = fmaf(e[rr].y, e[rr].y, ssv);
            ssv = fmaf(e[rr].z, e[rr].z, ssv);
            ssv = fmaf(e[rr].w, e[rr].w, ssv);
            V[rr][1] = ssv;
        }
        #pragma unroll
        for (int q = 0; q < 8; q++) {
            float4 wv = sWg4[q * 128 + j * 32 + lane];
            #pragma unroll
            for (int rr = 0; rr < 4; rr++) {
                float a = V[rr][2 + q];
                a = fmaf(e[rr].x, wv.x, a);
                a = fmaf(e[rr].y, wv.y, a);
                a = fmaf(e[rr].z, wv.z, a);
                a = fmaf(e[rr].w, wv.w, a);
                V[rr][2 + q] = a;
            }
        }
    }

    #pragma unroll
    for (int rr = 0; rr < 4; rr++)
        #pragma unroll
        for (int k = 0; k < 10; k++)
            V[rr][k] += __shfl_xor_sync(FULLMASK, V[rr][k], 16);
    bool up = (lane & 16) != 0;
    #pragma unroll
    for (int k = 0; k < 10; k++) {
        V[0][k] = up ? V[2][k] : V[0][k];
        V[1][k] = up ? V[3][k] : V[1][k];
    }
    #pragma unroll
    for (int k = 0; k < 10; k++) {
        V[0][k] += __shfl_xor_sync(FULLMASK, V[0][k], 8);
        V[1][k] += __shfl_xor_sync(FULLMASK, V[1][k], 8);
    }
    bool sel1 = (lane & 8) != 0;
    float A[10];
    #pragma unroll
    for (int k = 0; k < 10; k++) {
        float v = sel1 ? V[1][k] : V[0][k];
        v += __shfl_xor_sync(FULLMASK, v, 4);
        v += __shfl_xor_sync(FULLMASK, v, 2);
        v += __shfl_xor_sync(FULLMASK, v, 1);
        A[k] = v;
    }

    const float inv512 = 1.0f / 512.0f;
    float mu = A[0] * inv512;
    float var = fmaf(-mu, mu, A[1] * inv512);
    float inv = rsqrtf(var + 1e-5f);

    int j = lane & 7;
    int row = row0 + (lane >> 3);
    float ang = fmaf(inv, fmaf(-mu, sSg[j], A[2 + j]), sCq[j]);
    float s, c;
    __sincosf(0.5f * ang, &s, &c);
    if (row < B) d_cs[row * 8 + j] = make_float2(c, s);
}

// ============ Kernel 2: circuit + readout — 2 lanes/row, tan form ============
// Lane bit0 = q7. 16 rows/warp. Thread state: 64 u64 (128 amps):
// u64 index bits 0..4 = q0..q4, bit5 = q6; pair (lo,hi) = q5.
// RY(theta)=c(I+tJ); global cos factors folded into g table as F^2.
__global__ __launch_bounds__(256, 1) void circuit_kernel(float* __restrict__ out,
                                                         const float* __restrict__ theta,
                                                         const float* __restrict__ W_post,
                                                         const float* __restrict__ b_post,
                                                         int B) {
    __shared__ __align__(16) float2 sG2[2 * 66];
    __shared__ float sct[8], sst[8], sbp;

    int tid = threadIdx.x;
    if (tid < 8) {
        float h = 0.5f * theta[tid];
        sct[tid] = cosf(h);
        sst[tid] = sinf(h);
    }
    if (tid < 128) {
        float fa = 1.f;
        #pragma unroll
        for (int i = 0; i < 8; i++) {
            float cc = cosf(0.5f * theta[i]);
            fa *= cc * cc;
        }
        float scale = fa * fa;
        int l0 = tid >> 6, r = tid & 63;
        // basis bits: q0..q4 = r bits0-4, q6 = r bit5, q5 = pair, q7 = l0
        int b0 = (r & 31) | ((r & 32) << 1) | (l0 << 7);  // q5=0
        int b1 = b0 | 32;                                  // q5=1
        float g0 = 0.f, g1 = 0.f;
        #pragma unroll
        for (int i = 0; i < 8; i++) {
            float w = W_post[i];
            g0 += w * (((b0 >> i) & 1) ? -1.f : 1.f);
            g1 += w * (((b1 >> i) & 1) ? -1.f : 1.f);
        }
        sG2[l0 * 66 + r] = make_float2(g0 * scale, g1 * scale);
    }
    if (tid == 0) sbp = b_post[0];
    __syncthreads();

    int lane = tid & 31;
    int warp = blockIdx.x * 8 + (tid >> 5);
    int myrow = warp * 16 + (lane >> 1);
    int rowc = myrow < B ? myrow : (B - 1);
    int l0 = lane & 1;
    bool c7 = l0 != 0;

    // Load my row's (cos, sin) pairs
    const float4* ap = (const float4*)(d_cs + (size_t)rowc * 8);
    float4 v0 = ap[0], v1 = ap[1], v2 = ap[2], v3 = ap[3];
    float ca[8], sa[8];
    ca[0] = v0.x; sa[0] = v0.y; ca[1] = v0.z; sa[1] = v0.w;
    ca[2] = v1.x; sa[2] = v1.y; ca[3] = v1.z; sa[3] = v1.w;
    ca[4] = v2.x; sa[4] = v2.y; ca[5] = v2.z; sa[5] = v2.w;
    ca[6] = v3.x; sa[6] = v3.y; ca[7] = v3.z; sa[7] = v3.w;

    // Initial product state
    u64 amp2[64];
    {
        float w7 = l0 ? sa[7] : ca[7];
        amp2[0] = pk2(w7 * ca[5], w7 * sa[5]);
        #pragma unroll
        for (int q = 0; q < 5; q++) {   // q0..q4 -> bits 0..4
            u64 cab = pk2(ca[q], ca[q]);
            u64 sab = pk2(sa[q], sa[q]);
            const int cnt = 1 << q;
            #pragma unroll
            for (int r = 0; r < 16; r++) {
                if (r < cnt) {
                    amp2[r + cnt] = mul2(amp2[r], sab);
                    amp2[r]       = mul2(amp2[r], cab);
                }
            }
        }
        u64 ca6b = pk2(ca[6], ca[6]);
        u64 sa6b = pk2(sa[6], sa[6]);
        #pragma unroll
        for (int r = 0; r < 32; r++) {   // q6 -> bit5
            amp2[r + 32] = mul2(amp2[r], sa6b);
            amp2[r]      = mul2(amp2[r], ca6b);
        }
    }

    // tan-form constants
    float tq[8];
    #pragma unroll
    for (int q = 0; q < 8; q++) tq[q] = sst[q] / sct[q];
    u64 nt0b = pk2(-tq[0], -tq[0]), pt0b = pk2(tq[0], tq[0]);
    u64 ntb[5], ptb[5];
    #pragma unroll
    for (int q = 1; q < 5; q++) {
        ntb[q] = pk2(-tq[q], -tq[q]);
        ptb[q] = pk2(tq[q], tq[q]);
    }
    u64 t5v  = pk2(-tq[5], tq[5]);
    u64 nt6b = pk2(-tq[6], -tq[6]), pt6b = pk2(tq[6], tq[6]);
    float sg7t = l0 ? tq[7] : -tq[7];
    u64 sg7tb = pk2(sg7t, sg7t);

    #pragma unroll
    for (int d = 0; d < 2; d++) {
        // CNOT(0,1)..(3,4): register renames (free)
        #pragma unroll
        for (int r = 0; r < 64; r++)
            if ((r & 1) && !(r & 2)) { u64 t = amp2[r]; amp2[r] = amp2[r | 2]; amp2[r | 2] = t; }
        #pragma unroll
        for (int r = 0; r < 64; r++)
            if ((r & 2) && !(r & 4)) { u64 t = amp2[r]; amp2[r] = amp2[r | 4]; amp2[r | 4] = t; }
        #pragma unroll
        for (int r = 0; r < 64; r++)
            if ((r & 4) && !(r & 8)) { u64 t = amp2[r]; amp2[r] = amp2[r | 8]; amp2[r | 8] = t; }
        #pragma unroll
        for (int r = 0; r < 64; r++)
            if ((r & 8) && !(r & 16)) { u64 t = amp2[r]; amp2[r] = amp2[r | 16]; amp2[r | 16] = t; }
        // fused CNOT(4,5) [bit4=1: swap lo/hi] + CNOT(5,6) [exchange hi words r <-> r|32]
        #pragma unroll
        for (int r = 0; r < 32; r++) {
            float alo, ahi, blo, bhi;
            up2(amp2[r], alo, ahi);
            up2(amp2[r + 32], blo, bhi);
            if ((r & 16) == 0) {
                amp2[r]      = pk2(alo, bhi);
                amp2[r + 32] = pk2(blo, ahi);
            } else {
                amp2[r]      = pk2(ahi, blo);
                amp2[r + 32] = pk2(bhi, alo);
            }
        }
        // CNOT(6,7): q6=1 regs (bit5=1) gather partner lane (q7 flip)
        #pragma unroll
        for (int r = 32; r < 64; r++) {
            float lo, hi;
            up2(amp2[r], lo, hi);
            lo = __shfl_xor_sync(FULLMASK, lo, 1);
            hi = __shfl_xor_sync(FULLMASK, hi, 1);
            amp2[r] = pk2(lo, hi);
        }
        // fused CNOT(7,0)+RY(0), tan form
        #pragma unroll
        for (int r = 0; r < 64; r += 2) {
            u64 a0 = amp2[r], a1 = amp2[r + 1];
            u64 x0 = c7 ? a1 : a0;
            u64 x1 = c7 ? a0 : a1;
            amp2[r]     = fma2(nt0b, x1, x0);
            amp2[r + 1] = fma2(pt0b, x0, x1);
        }
        // RY(1..4), tan form
        #pragma unroll
        for (int q = 1; q < 5; q++) {
            const int bq = 1 << q;
            #pragma unroll
            for (int r = 0; r < 64; r++) {
                if (!(r & bq)) {
                    int r2 = r | bq;
                    u64 a0 = amp2[r], a1 = amp2[r2];
                    amp2[r]  = fma2(ntb[q], a1, a0);
                    amp2[r2] = fma2(ptb[q], a0, a1);
                }
            }
        }
        // RY(5): within-pair
        #pragma unroll
        for (int r = 0; r < 64; r++) {
            float lo, hi;
            up2(amp2[r], lo, hi);
            amp2[r] = fma2(t5v, pk2(hi, lo), amp2[r]);
        }
        // RY(6): register pairs (r, r+32)
        #pragma unroll
        for (int r = 0; r < 32; r++) {
            u64 a0 = amp2[r], a1 = amp2[r + 32];
            amp2[r]      = fma2(nt6b, a1, a0);
            amp2[r + 32] = fma2(pt6b, a0, a1);
        }
        // RY(7): lane
        #pragma unroll
        for (int r = 0; r < 64; r++) {
            float lo, hi;
            up2(amp2[r], lo, hi);
            float plo = __shfl_xor_sync(FULLMASK, lo, 1);
            float phi = __shfl_xor_sync(FULLMASK, hi, 1);
            amp2[r] = fma2(sg7tb, pk2(plo, phi), amp2[r]);
        }
    }

    // Readout (g table carries F^2)
    const u64* gp = (const u64*)(sG2 + l0 * 66);
    u64 tot2 = pk2(0.f, 0.f);
    #pragma unroll
    for (int r = 0; r < 64; r++) {
        u64 p2 = mul2(amp2[r], amp2[r]);
        tot2 = fma2(p2, gp[r], tot2);
    }
    float tlo, thi;
    up2(tot2, tlo, thi);
    float tot = tlo + thi;
    tot += __shfl_xor_sync(FULLMASK, tot, 1);

    if (l0 == 0 && myrow < B)
        out[myrow] = tot + sbp;
}

extern "C" void kernel_launch(void* const* d_in, const int* in_sizes, int n_in,
                              void* d_out, int out_size) {
    const float* E        = (const float*)d_in[0];
    const float* ln_gamma = (const float*)d_in[1];
    const float* ln_beta  = (const float*)d_in[2];
    const float* W_pre    = (const float*)d_in[3];
    const float* b_pre    = (const float*)d_in[4];
    const float* theta    = (const float*)d_in[5];
    const float* W_post   = (const float*)d_in[6];
    const float* b_post   = (const float*)d_in[7];
    float* out = (float*)d_out;
    int B = out_size;

    angles_kernel<<<(B + 31) / 32, 256>>>(E, W_pre, ln_gamma, ln_beta, b_pre, B);
    circuit_kernel<<<(B + 127) / 128, 256>>>(out, theta, W_post, b_post, B);
}

// round 13
// speedup vs baseline: 1.1857x; 1.0591x over previous
#include <cuda_runtime.h>
#include <cstdint>

#define FULLMASK 0xffffffffu
typedef unsigned long long u64;

// ---- f32x2 packed helpers (sm_103a) ----
__device__ __forceinline__ u64 pk2(float lo, float hi) {
    u64 r; asm("mov.b64 %0,{%1,%2};" : "=l"(r) : "f"(lo), "f"(hi)); return r;
}
__device__ __forceinline__ void up2(u64 v, float& lo, float& hi) {
    asm("mov.b64 {%0,%1},%2;" : "=f"(lo), "=f"(hi) : "l"(v));
}
__device__ __forceinline__ u64 fma2(u64 a, u64 b, u64 c) {
    u64 d; asm("fma.rn.f32x2 %0,%1,%2,%3;" : "=l"(d) : "l"(a), "l"(b), "l"(c)); return d;
}
__device__ __forceinline__ u64 mul2(u64 a, u64 b) {
    u64 d; asm("mul.rn.f32x2 %0,%1,%2;" : "=l"(d) : "l"(a), "l"(b)); return d;
}

// ============ Fused kernel: LN+linear (angles) -> smem handoff -> circuit ============
// Block = 256 threads = 8 warps = 64 rows.
// Phase 1: per warp, 2 groups of 4 rows (verified routed-reduction datapath);
//          (cos,sin)(angle/2) written to smem scs (stride 10 float2 = conflict-free).
// Phase 2: R11 circuit: 4 lanes/row, 32 x f32x2/thread (pair = q5), tan-form gates,
//          global cos factors folded into g table as F^2.
__global__ __launch_bounds__(256, 2) void qsco_fused(const float* __restrict__ E,
                                                     const float* __restrict__ W_pre,
                                                     const float* __restrict__ ln_gamma,
                                                     const float* __restrict__ ln_beta,
                                                     const float* __restrict__ b_pre,
                                                     const float* __restrict__ theta,
                                                     const float* __restrict__ W_post,
                                                     const float* __restrict__ b_post,
                                                     float* __restrict__ out,
                                                     int B) {
    __shared__ float4 sWg4[8 * 128];            // 16 KB: gamma ⊙ W_pre
    __shared__ float sGw[32], sBw[32];
    __shared__ float sSg[8], sCq[8];
    __shared__ __align__(16) float2 scs[64 * 10];  // (c,s) per row, stride 10 -> no bank conflicts
    __shared__ __align__(16) float2 sG2[4 * 34];
    __shared__ float sct[8], sst[8], sbp;

    int tid = threadIdx.x;
    int lane = tid & 31;
    int wrp = tid >> 5;

    // ---- block-constant prep (weights + Sg/Cq + trig + g table) ----
    {
        const float4* Wp4 = (const float4*)W_pre;
        const float4* g4  = (const float4*)ln_gamma;
        const float4* b4  = (const float4*)ln_beta;
        float gw[4], bw[4];
        #pragma unroll
        for (int j = 0; j < 4; j++) {
            int i = tid + 256 * j;
            float4 w = Wp4[i];
            float4 g = g4[i & 127];
            float4 b = b4[i & 127];
            float gsum = 0.f, bsum = 0.f;
            gsum = fmaf(g.x, w.x, gsum); gsum = fmaf(g.y, w.y, gsum);
            gsum = fmaf(g.z, w.z, gsum); gsum = fmaf(g.w, w.w, gsum);
            bsum = fmaf(b.x, w.x, bsum); bsum = fmaf(b.y, w.y, bsum);
            bsum = fmaf(b.z, w.z, bsum); bsum = fmaf(b.w, w.w, bsum);
            gw[j] = gsum; bw[j] = bsum;
            w.x *= g.x; w.y *= g.y; w.z *= g.z; w.w *= g.w;
            sWg4[i] = w;
        }
        #pragma unroll
        for (int m = 16; m; m >>= 1) {
            #pragma unroll
            for (int j = 0; j < 4; j++) {
                gw[j] += __shfl_xor_sync(FULLMASK, gw[j], m);
                bw[j] += __shfl_xor_sync(FULLMASK, bw[j], m);
            }
        }
        if (lane == 0) {
            #pragma unroll
            for (int j = 0; j < 4; j++) {
                sGw[wrp * 4 + j] = gw[j];
                sBw[wrp * 4 + j] = bw[j];
            }
        }
        if (tid < 8) {
            float h = 0.5f * theta[tid];
            sct[tid] = cosf(h);
            sst[tid] = sinf(h);
        }
        if (tid >= 128 && tid < 256) {
            int t = tid - 128;
            float fa = 1.f;
            #pragma unroll
            for (int i = 0; i < 8; i++) {
                float cc = cosf(0.5f * theta[i]);
                fa *= cc * cc;
            }
            float scale = fa * fa;
            int lsub = t >> 5, r = t & 31;
            int bb0 = r | (lsub << 6);
            int bb1 = bb0 | 32;
            float g0 = 0.f, g1 = 0.f;
            #pragma unroll
            for (int i = 0; i < 8; i++) {
                float w = W_post[i];
                g0 += w * (((bb0 >> i) & 1) ? -1.f : 1.f);
                g1 += w * (((bb1 >> i) & 1) ? -1.f : 1.f);
            }
            sG2[lsub * 34 + r] = make_float2(g0 * scale, g1 * scale);
        }
        if (tid == 16) sbp = b_post[0];
    }
    __syncthreads();
    if (tid < 8) {
        int h = tid & 1, jj = tid >> 1;
        float s = 0.f, cc = 0.f;
        #pragma unroll
        for (int m = 0; m < 4; m++) {
            s  += sGw[(4 * h + m) * 4 + jj];
            cc += sBw[(4 * h + m) * 4 + jj];
        }
        sSg[tid] = s;
        sCq[tid] = cc + b_pre[tid];
    }
    __syncthreads();

    int blkrow0 = blockIdx.x * 64;

    // ---- Phase 1: angles for 8 rows per warp (2 groups of 4) ----
    #pragma unroll
    for (int g = 0; g < 2; g++) {
        int row0 = blkrow0 + wrp * 8 + g * 4;

        float V[4][10];
        #pragma unroll
        for (int rr = 0; rr < 4; rr++)
            #pragma unroll
            for (int k = 0; k < 10; k++) V[rr][k] = 0.f;

        const float4* er[4];
        #pragma unroll
        for (int rr = 0; rr < 4; rr++) {
            int r = row0 + rr;
            if (r >= B) r = B - 1;
            er[rr] = (const float4*)(E + (size_t)r * 512);
        }

        #pragma unroll
        for (int j = 0; j < 4; j++) {
            float4 e[4];
            #pragma unroll
            for (int rr = 0; rr < 4; rr++) e[rr] = __ldcs(&er[rr][j * 32 + lane]);
            #pragma unroll
            for (int rr = 0; rr < 4; rr++) {
                V[rr][0] += (e[rr].x + e[rr].y) + (e[rr].z + e[rr].w);
                float ssv = V[rr][1];
                ssv = fmaf(e[rr].x, e[rr].x, ssv);
                ssv = fmaf(e[rr].y, e[rr].y, ssv);
                ssv = fmaf(e[rr].z, e[rr].z, ssv);
                ssv = fmaf(e[rr].w, e[rr].w, ssv);
                V[rr][1] = ssv;
            }
            #pragma unroll
            for (int q = 0; q < 8; q++) {
                float4 wv = sWg4[q * 128 + j * 32 + lane];
                #pragma unroll
                for (int rr = 0; rr < 4; rr++) {
                    float a = V[rr][2 + q];
                    a = fmaf(e[rr].x, wv.x, a);
                    a = fmaf(e[rr].y, wv.y, a);
                    a = fmaf(e[rr].z, wv.z, a);
                    a = fmaf(e[rr].w, wv.w, a);
                    V[rr][2 + q] = a;
                }
            }
        }

        // Routed reduction: lane ends with row (lane>>3)'s 10 sums
        #pragma unroll
        for (int rr = 0; rr < 4; rr++)
            #pragma unroll
            for (int k = 0; k < 10; k++)
                V[rr][k] += __shfl_xor_sync(FULLMASK, V[rr][k], 16);
        bool up = (lane & 16) != 0;
        #pragma unroll
        for (int k = 0; k < 10; k++) {
            V[0][k] = up ? V[2][k] : V[0][k];
            V[1][k] = up ? V[3][k] : V[1][k];
        }
        #pragma unroll
        for (int k = 0; k < 10; k++) {
            V[0][k] += __shfl_xor_sync(FULLMASK, V[0][k], 8);
            V[1][k] += __shfl_xor_sync(FULLMASK, V[1][k], 8);
        }
        bool sel1 = (lane & 8) != 0;
        float A[10];
        #pragma unroll
        for (int k = 0; k < 10; k++) {
            float v = sel1 ? V[1][k] : V[0][k];
            v += __shfl_xor_sync(FULLMASK, v, 4);
            v += __shfl_xor_sync(FULLMASK, v, 2);
            v += __shfl_xor_sync(FULLMASK, v, 1);
            A[k] = v;
        }

        const float inv512 = 1.0f / 512.0f;
        float mu = A[0] * inv512;
        float var = fmaf(-mu, mu, A[1] * inv512);
        float inv = rsqrtf(var + 1e-5f);

        int j = lane & 7;
        float ang = fmaf(inv, fmaf(-mu, sSg[j], A[2 + j]), sCq[j]);
        float s, c;
        __sincosf(0.5f * ang, &s, &c);
        int rowInBlk = wrp * 8 + g * 4 + (lane >> 3);
        scs[rowInBlk * 10 + j] = make_float2(c, s);
    }
    __syncthreads();

    // ---- Phase 2: circuit (R11, tan-form) ----
    int warp = blockIdx.x * 8 + wrp;
    int myrow = warp * 8 + (lane >> 2);
    int rowInBlk = wrp * 8 + (lane >> 2);

    const float4* ap = (const float4*)&scs[rowInBlk * 10];
    float4 v0 = ap[0], v1 = ap[1], v2 = ap[2], v3 = ap[3];
    float ca[8], sa[8];
    ca[0] = v0.x; sa[0] = v0.y; ca[1] = v0.z; sa[1] = v0.w;
    ca[2] = v1.x; sa[2] = v1.y; ca[3] = v1.z; sa[3] = v1.w;
    ca[4] = v2.x; sa[4] = v2.y; ca[5] = v2.z; sa[5] = v2.w;
    ca[6] = v3.x; sa[6] = v3.y; ca[7] = v3.z; sa[7] = v3.w;

    int b6 = lane & 1;
    int b7 = (lane >> 1) & 1;
    bool c7 = b7 != 0;
    int lbase = lane & ~3;
    int s0 = lbase | b6 | ((b7 ^ b6) << 1);
    int s1 = s0 ^ 1;

    // Initial product state (packed over qubit5)
    u64 amp2[32];
    {
        float w67 = (b6 ? sa[6] : ca[6]) * (b7 ? sa[7] : ca[7]);
        amp2[0] = pk2(w67 * ca[5], w67 * sa[5]);
        #pragma unroll
        for (int q = 0; q < 5; q++) {
            u64 cab = pk2(ca[q], ca[q]);
            u64 sab = pk2(sa[q], sa[q]);
            const int cnt = 1 << q;
            #pragma unroll
            for (int r = 0; r < 16; r++) {
                if (r < cnt) {
                    amp2[r + cnt] = mul2(amp2[r], sab);
                    amp2[r]       = mul2(amp2[r], cab);
                }
            }
        }
    }

    // tan-form constants
    float tq[8];
    #pragma unroll
    for (int q = 0; q < 8; q++) tq[q] = sst[q] / sct[q];
    u64 nt0b = pk2(-tq[0], -tq[0]), pt0b = pk2(tq[0], tq[0]);
    u64 ntb[5], ptb[5];
    #pragma unroll
    for (int q = 1; q < 5; q++) {
        ntb[q] = pk2(-tq[q], -tq[q]);
        ptb[q] = pk2(tq[q], tq[q]);
    }
    u64 t5v = pk2(-tq[5], tq[5]);
    float sg6t = b6 ? tq[6] : -tq[6];
    float sg7t = b7 ? tq[7] : -tq[7];
    u64 sg6tb = pk2(sg6t, sg6t);
    u64 sg7tb = pk2(sg7t, sg7t);

    #pragma unroll
    for (int d = 0; d < 2; d++) {
        // CNOT(0,1)..(3,4): register renames (free)
        #pragma unroll
        for (int r = 0; r < 32; r++)
            if ((r & 1) && !(r & 2)) { u64 t = amp2[r]; amp2[r] = amp2[r | 2]; amp2[r | 2] = t; }
        #pragma unroll
        for (int r = 0; r < 32; r++)
            if ((r & 2) && !(r & 4)) { u64 t = amp2[r]; amp2[r] = amp2[r | 4]; amp2[r | 4] = t; }
        #pragma unroll
        for (int r = 0; r < 32; r++)
            if ((r & 4) && !(r & 8)) { u64 t = amp2[r]; amp2[r] = amp2[r | 8]; amp2[r | 8] = t; }
        #pragma unroll
        for (int r = 0; r < 32; r++)
            if ((r & 8) && !(r & 16)) { u64 t = amp2[r]; amp2[r] = amp2[r | 16]; amp2[r | 16] = t; }
        // CNOT(4,5) absorbed half-swap + merged CNOT(5,6)+(6,7) lane gather
        #pragma unroll
        for (int r = 0; r < 32; r++) {
            float lo, hi;
            up2(amp2[r], lo, hi);
            float x0 = (r & 16) ? hi : lo;
            float x1 = (r & 16) ? lo : hi;
            float nlo = __shfl_sync(FULLMASK, x0, s0);
            float nhi = __shfl_sync(FULLMASK, x1, s1);
            amp2[r] = pk2(nlo, nhi);
        }
        // fused CNOT(7,0)+RY(0), tan form
        #pragma unroll
        for (int r = 0; r < 32; r += 2) {
            u64 a0 = amp2[r], a1 = amp2[r + 1];
            u64 x0 = c7 ? a1 : a0;
            u64 x1 = c7 ? a0 : a1;
            amp2[r]     = fma2(nt0b, x1, x0);
            amp2[r + 1] = fma2(pt0b, x0, x1);
        }
        // RY(1..4), tan form
        #pragma unroll
        for (int q = 1; q < 5; q++) {
            const int bq = 1 << q;
            #pragma unroll
            for (int r = 0; r < 32; r++) {
                if (!(r & bq)) {
                    int r2 = r | bq;
                    u64 a0 = amp2[r], a1 = amp2[r2];
                    amp2[r]  = fma2(ntb[q], a1, a0);
                    amp2[r2] = fma2(ptb[q], a0, a1);
                }
            }
        }
        // RY(5): within-pair
        #pragma unroll
        for (int r = 0; r < 32; r++) {
            float lo, hi;
            up2(amp2[r], lo, hi);
            amp2[r] = fma2(t5v, pk2(hi, lo), amp2[r]);
        }
        // RY(6): lane xor1
        #pragma unroll
        for (int r = 0; r < 32; r++) {
            float lo, hi;
            up2(amp2[r], lo, hi);
            float plo = __shfl_xor_sync(FULLMASK, lo, 1);
            float phi = __shfl_xor_sync(FULLMASK, hi, 1);
            amp2[r] = fma2(sg6tb, pk2(plo, phi), amp2[r]);
        }
        // RY(7): lane xor2
        #pragma unroll
        for (int r = 0; r < 32; r++) {
            float lo, hi;
            up2(amp2[r], lo, hi);
            float plo = __shfl_xor_sync(FULLMASK, lo, 2);
            float phi = __shfl_xor_sync(FULLMASK, hi, 2);
            amp2[r] = fma2(sg7tb, pk2(plo, phi), amp2[r]);
        }
    }

    // Readout (g table carries F^2)
    int lsub = lane & 3;
    const u64* gp = (const u64*)(sG2 + lsub * 34);
    u64 tot2 = pk2(0.f, 0.f);
    #pragma unroll
    for (int r = 0; r < 32; r++) {
        u64 p2 = mul2(amp2[r], amp2[r]);
        tot2 = fma2(p2, gp[r], tot2);
    }
    float tlo, thi;
    up2(tot2, tlo, thi);
    float tot = tlo + thi;
    tot += __shfl_xor_sync(FULLMASK, tot, 1);
    tot += __shfl_xor_sync(FULLMASK, tot, 2);

    if (lsub == 0 && myrow < B)
        out[myrow] = tot + sbp;
}

extern "C" void kernel_launch(void* const* d_in, const int* in_sizes, int n_in,
                              void* d_out, int out_size) {
    const float* E        = (const float*)d_in[0];
    const float* ln_gamma = (const float*)d_in[1];
    const float* ln_beta  = (const float*)d_in[2];
    const float* W_pre    = (const float*)d_in[3];
    const float* b_pre    = (const float*)d_in[4];
    const float* theta    = (const float*)d_in[5];
    const float* W_post   = (const float*)d_in[6];
    const float* b_post   = (const float*)d_in[7];
    float* out = (float*)d_out;
    int B = out_size;

    qsco_fused<<<(B + 63) / 64, 256>>>(E, W_pre, ln_gamma, ln_beta, b_pre,
                                       theta, W_post, b_post, out, B);
}